// round 3
// baseline (speedup 1.0000x reference)
#include <cuda_runtime.h>
#include <cstdint>
#include <math.h>

#define FULL 0xffffffffu

// exact integer sqrt (floor) for v in [0, 4096]; returns -1 for v < 0
__device__ __forceinline__ int isqrt_i(int v) {
    if (v < 0) return -1;
    int a = (int)sqrtf((float)v);
    while ((a + 1) * (a + 1) <= v) a++;
    while (a * a > v) a--;
    return a;
}

// SMEM layout (dynamic):
//   sdata : 16384 bytes  (quantized channel image, u8)
//   sh8   : 65536 bytes  (8 warps x 256 bins x 32 lanes, u8 counts)
//   wsum  : 8*256 u32    (per-warp per-bin sums)
//   hist4 : 4*256 u32    (per-ring 256-bin histogram)
static constexpr int SMEM_BYTES = 16384 + 65536 + 8 * 256 * 4 + 4 * 256 * 4;

__global__ __launch_bounds__(256, 2)
void radial_tokenizer_kernel(const float* __restrict__ img, float* __restrict__ out) {
    extern __shared__ uint8_t smem[];
    uint8_t*  sdata = smem;                                    // 16384
    uint8_t*  sh8   = smem + 16384;                            // 65536
    uint32_t* wsum  = (uint32_t*)(smem + 16384 + 65536);       // 8*256
    uint32_t* hist4 = wsum + 8 * 256;                          // 4*256

    const int tid  = threadIdx.x;
    const int lane = tid & 31;
    const int wid  = tid >> 5;
    const int blk  = blockIdx.x;  // b*3 + c

    // ---- Phase A: zero hist + stage quantized bytes (overlapped) ----
    const float4* in4 = (const float4*)(img + (size_t)blk * 16384);
    uint32_t* sd32 = (uint32_t*)sdata;

    uint4* z4 = (uint4*)sh8;
    #pragma unroll
    for (int i = 0; i < 16; i++)
        z4[i * 256 + tid] = make_uint4(0u, 0u, 0u, 0u);

    #pragma unroll 8
    for (int i = 0; i < 16; i++) {
        float4 f = in4[i * 256 + tid];
        uint32_t p = (uint32_t)(int)(f.x * 255.0f)
                   | ((uint32_t)(int)(f.y * 255.0f) << 8)
                   | ((uint32_t)(int)(f.z * 255.0f) << 16)
                   | ((uint32_t)(int)(f.w * 255.0f) << 24);
        sd32[i * 256 + tid] = p;
    }
    __syncthreads();

    // ---- Phase B: per-warp privatized histogram over assigned ring rows ----
    // warp -> ring assignment proportional to ring size (~1:3:5:7): {0,1,1,2,2,3,3,3}
    int ring, wIdx, nW;
    if (wid == 0)      { ring = 0; wIdx = 0;       nW = 1; }
    else if (wid < 3)  { ring = 1; wIdx = wid - 1; nW = 2; }
    else if (wid < 5)  { ring = 2; wIdx = wid - 3; nW = 2; }
    else               { ring = 3; wIdx = wid - 5; nW = 3; }

    const int R1   = (ring + 1) * 16;
    const int r1sq = R1 * R1;
    const int r0   = ring * 16;
    const int r0sq = r0 * r0;
    const int y0   = 64 - R1;
    const int y1   = min(127, 64 + R1);
    uint8_t* myhist = sh8 + wid * 8192;

    for (int y = y0 + wIdx; y <= y1; y += nW) {
        const int dy  = y - 64;
        const int dy2 = dy * dy;
        const int a = isqrt_i(r1sq - dy2);      // max |dx| inside outer circle
        const int b = isqrt_i(r0sq - dy2);      // max |dx| inside inner circle (-1: no hole)
        int lo1, n1, lo2, n2;
        if (b >= 0) {
            lo1 = 64 - a;  n1 = a - b;           // [64-a, 63-b]
            lo2 = 65 + b;                        // [65+b, min(127, 64+a)]
            n2  = min(127, 64 + a) - lo2 + 1;
            if (n1 < 0) n1 = 0;
            if (n2 < 0) n2 = 0;
        } else {
            lo1 = 64 - a;
            n1  = min(127, 64 + a) - lo1 + 1;    // full span
            lo2 = 0; n2 = 0;
        }
        const int npx = n1 + n2;
        const uint8_t* row = sdata + (y << 7);
        for (int p0 = 0; p0 < npx; p0 += 32) {
            int p = p0 + lane;
            if (p < npx) {
                int x = (p < n1) ? (lo1 + p) : (lo2 + (p - n1));
                unsigned v = row[x];
                myhist[v * 32 + lane]++;   // non-atomic: (bin,lane) owned by this thread
            }
        }
    }
    __syncwarp();

    // ---- Phase C1: per-warp lane-reduction (32 uint8 -> 1 u32 per bin) via dp4a ----
    #pragma unroll
    for (int j = 0; j < 8; j++) {
        int bin = j * 32 + lane;
        const uint4* q = (const uint4*)(myhist + bin * 32);
        uint4 q0 = q[0], q1 = q[1];
        unsigned s = 0;
        s = __dp4a(q0.x, 0x01010101u, s);
        s = __dp4a(q0.y, 0x01010101u, s);
        s = __dp4a(q0.z, 0x01010101u, s);
        s = __dp4a(q0.w, 0x01010101u, s);
        s = __dp4a(q1.x, 0x01010101u, s);
        s = __dp4a(q1.y, 0x01010101u, s);
        s = __dp4a(q1.z, 0x01010101u, s);
        s = __dp4a(q1.w, 0x01010101u, s);
        wsum[wid * 256 + bin] = s;
    }
    __syncthreads();

    // ---- Phase C2: combine warps of each ring into hist4 ----
    #pragma unroll
    for (int pair = tid; pair < 1024; pair += 256) {
        int r   = pair >> 8;
        int bin = pair & 255;
        int wst  = (r == 0) ? 0 : (r == 1) ? 1 : (r == 2) ? 3 : 5;
        int wcnt = (r == 0) ? 1 : (r == 3) ? 3 : 2;
        unsigned s = 0;
        for (int w = 0; w < wcnt; w++) s += wsum[(wst + w) * 256 + bin];
        hist4[pair] = s;
    }
    __syncthreads();

    // ---- Phase D: stats (mean/std/median) — one warp per ring ----
    if (wid < 4) {
        const int r = wid;
        unsigned c[8];
        unsigned cnt = 0, sum = 0, sq = 0;
        #pragma unroll
        for (int i = 0; i < 8; i++) {
            unsigned v = (unsigned)lane * 8u + i;
            c[i] = hist4[r * 256 + v];
            cnt += c[i];
            sum += c[i] * v;
            sq  += c[i] * v * v;
        }
        // inclusive warp scan of counts
        unsigned csum = cnt;
        #pragma unroll
        for (int d = 1; d < 32; d <<= 1) {
            unsigned t = __shfl_up_sync(FULL, csum, d);
            if (lane >= d) csum += t;
        }
        unsigned pexcl = csum - cnt;
        unsigned n    = __shfl_sync(FULL, csum, 31);
        unsigned tsum = __reduce_add_sync(FULL, sum);
        unsigned tsq  = __reduce_add_sync(FULL, sq);

        unsigned k1 = (n - 1) >> 1, k2 = n >> 1;  // median ranks (0-based)
        int v1 = -1, v2 = -1;
        if (k1 >= pexcl && k1 < csum) {
            unsigned run = pexcl;
            #pragma unroll
            for (int i = 0; i < 8; i++) { run += c[i]; if (v1 < 0 && k1 < run) v1 = lane * 8 + i; }
        }
        if (k2 >= pexcl && k2 < csum) {
            unsigned run = pexcl;
            #pragma unroll
            for (int i = 0; i < 8; i++) { run += c[i]; if (v2 < 0 && k2 < run) v2 = lane * 8 + i; }
        }
        v1 = __reduce_max_sync(FULL, v1);
        v2 = __reduce_max_sync(FULL, v2);

        if (lane == 0) {
            int bb = blk / 3, cc = blk - bb * 3;
            double dn   = (double)n;
            double mean = (double)tsum / dn;
            double var  = (double)tsq / dn - mean * mean;
            float stdv  = (float)sqrt(var > 0.0 ? var : 0.0);
            float med   = 0.5f * (float)(v1 + v2);
            float* o = out + ((size_t)bb * 4 + r) * 9;
            o[cc]     = (float)mean;
            o[3 + cc] = stdv;
            o[6 + cc] = med;
        }
    }
}

extern "C" void kernel_launch(void* const* d_in, const int* in_sizes, int n_in,
                              void* d_out, int out_size) {
    const float* img = (const float*)d_in[0];
    float* out = (float*)d_out;
    const int nblk = in_sizes[0] / 16384;  // B * 3 CTAs (one per batch-channel)
    cudaFuncSetAttribute(radial_tokenizer_kernel,
                         cudaFuncAttributeMaxDynamicSharedMemorySize, SMEM_BYTES);
    radial_tokenizer_kernel<<<nblk, 256, SMEM_BYTES>>>(img, out);
}

// round 6
// speedup vs baseline: 1.7749x; 1.7749x over previous
#include <cuda_runtime.h>
#include <cstdint>
#include <math.h>

#define FULL 0xffffffffu

// exact integer sqrt (floor) for v in [0, 4096]; returns -1 for v < 0
__device__ __forceinline__ int isqrt_i(int v) {
    if (v < 0) return -1;
    int a = (int)sqrtf((float)v);
    while ((a + 1) * (a + 1) <= v) a++;
    while (a * a > v) a--;
    return a;
}

// SMEM layout (dynamic):
//   sh4    : 32768 bytes  (8 warps x 128 byte-rows x 32 lanes; 2 bins/byte as nibbles)
//   hist4  : 4*256 u32    (per-ring combined histogram)
//   rowtab : 512 u32      (per ring x row: lo1 | n1<<8 | lo2<<16 | n2<<24)
static constexpr int SMEM_BYTES = 32768 + 4 * 256 * 4 + 512 * 4;  // 38912 < 48KB

__global__ __launch_bounds__(256, 5)
void radial_tokenizer_kernel(const float* __restrict__ img, float* __restrict__ out) {
    extern __shared__ uint8_t smem[];
    uint8_t*  sh4    = smem;                               // 32768
    uint32_t* hist4  = (uint32_t*)(smem + 32768);          // 1024 words
    uint32_t* rowtab = hist4 + 1024;                       // 512 words

    const int tid  = threadIdx.x;
    const int lane = tid & 31;
    const int wid  = tid >> 5;
    const int blk  = blockIdx.x;  // b*3 + c

    // ---- Phase 0: zero hists + build row-interval table (parallel, once) ----
    {
        uint4 z = make_uint4(0u, 0u, 0u, 0u);
        uint4* z4 = (uint4*)sh4;
        #pragma unroll
        for (int i = 0; i < 8; i++) z4[i * 256 + tid] = z;
        ((uint4*)hist4)[tid] = z;
    }
    for (int e = tid; e < 512; e += 256) {
        int r  = e >> 7;
        int y  = e & 127;
        int R1 = (r + 1) * 16;
        int dy = y - 64;
        int ao = R1 * R1 - dy * dy;
        uint32_t ent = 0;
        if (ao >= 0) {
            int a  = isqrt_i(ao);
            int bi = isqrt_i(r * 16 * r * 16 - dy * dy);
            int lo1, n1, lo2, n2;
            if (bi >= 0) {
                lo1 = 64 - a;  n1 = a - bi;
                lo2 = 65 + bi; n2 = min(127, 64 + a) - lo2 + 1;
                if (n1 < 0) n1 = 0;
                if (n2 < 0) n2 = 0;
            } else {
                lo1 = 64 - a;
                n1  = min(127, 64 + a) - lo1 + 1;
                lo2 = 0; n2 = 0;
            }
            ent = (uint32_t)lo1 | ((uint32_t)n1 << 8) | ((uint32_t)lo2 << 16) | ((uint32_t)n2 << 24);
        }
        rowtab[e] = ent;
    }
    __syncthreads();

    // ---- Phase B: per-warp privatized nibble histogram, direct from gmem ----
    // warp -> ring assignment proportional to ring size (~1:3:5:7): {0,1,1,2,2,3,3,3}
    int ring, wIdx, nW;
    if (wid == 0)      { ring = 0; wIdx = 0;       nW = 1; }
    else if (wid < 3)  { ring = 1; wIdx = wid - 1; nW = 2; }
    else if (wid < 5)  { ring = 2; wIdx = wid - 3; nW = 2; }
    else               { ring = 3; wIdx = wid - 5; nW = 3; }

    const int R1 = (ring + 1) * 16;
    const int y0 = (ring == 3) ? 0   : (64 - R1);
    const int y1 = (ring == 3) ? 127 : (64 + R1);
    uint8_t* myh = sh4 + wid * 4096;
    const float* base = img + (size_t)blk * 16384;
    const uint32_t* tab = rowtab + ring * 128;

    for (int y = y0 + wIdx; y <= y1; y += nW) {
        const uint32_t e = tab[y];
        const int lo1 = e & 0xff;
        const int n1  = (e >> 8) & 0xff;
        const int lo2 = (e >> 16) & 0xff;
        const int npx = n1 + (int)(e >> 24);
        const float* row = base + (y << 7);

        float f[4];
        #pragma unroll
        for (int k = 0; k < 4; k++) {               // batch loads -> MLP 4
            int p = lane + (k << 5);
            int x = (p < n1) ? (lo1 + p) : (lo2 + p - n1);
            f[k] = (p < npx) ? row[x] : 0.0f;
        }
        #pragma unroll
        for (int k = 0; k < 4; k++) {
            int p = lane + (k << 5);
            if (p < npx) {
                unsigned v = (unsigned)(int)(f[k] * 255.0f);       // floor, v in [0,254]
                unsigned off = ((v >> 1) << 5) | (unsigned)lane;   // byte; 2 bins/byte
                unsigned inc = 1u << ((v & 1u) << 2);              // 1 or 16
                myh[off] = (uint8_t)(myh[off] + inc);              // non-atomic: cell owned
            }
        }
    }
    __syncwarp();

    // ---- Phase C: nibble lane-reduction via dp4a, combine into hist4 (smem atomics) ----
    uint32_t* rh = hist4 + ring * 256;
    #pragma unroll
    for (int j = 0; j < 4; j++) {
        int bp = lane + j * 32;  // byte-row 0..127 -> bins 2bp (low nib), 2bp+1 (high nib)
        const uint4* q = (const uint4*)(myh + bp * 32);
        uint4 a = q[0], b = q[1];
        unsigned lo = 0, hi = 0;
        unsigned w;
        #define ACC(W) w = (W); \
            lo = __dp4a(w & 0x0F0F0F0Fu, 0x01010101u, lo); \
            hi = __dp4a((w >> 4) & 0x0F0F0F0Fu, 0x01010101u, hi);
        ACC(a.x) ACC(a.y) ACC(a.z) ACC(a.w)
        ACC(b.x) ACC(b.y) ACC(b.z) ACC(b.w)
        #undef ACC
        atomicAdd(rh + 2 * bp,     lo);
        atomicAdd(rh + 2 * bp + 1, hi);
    }
    __syncthreads();

    // ---- Phase D: stats (mean/std/median) — one warp per ring ----
    if (wid < 4) {
        const int r = wid;
        unsigned c[8];
        unsigned cnt = 0, sum = 0, sq = 0;
        #pragma unroll
        for (int i = 0; i < 8; i++) {
            unsigned v = (unsigned)lane * 8u + i;
            c[i] = hist4[r * 256 + v];
            cnt += c[i];
            sum += c[i] * v;
            sq  += c[i] * v * v;
        }
        // inclusive warp scan of counts
        unsigned csum = cnt;
        #pragma unroll
        for (int d = 1; d < 32; d <<= 1) {
            unsigned t = __shfl_up_sync(FULL, csum, d);
            if (lane >= d) csum += t;
        }
        unsigned pexcl = csum - cnt;
        unsigned n    = __shfl_sync(FULL, csum, 31);
        unsigned tsum = __reduce_add_sync(FULL, sum);
        unsigned tsq  = __reduce_add_sync(FULL, sq);

        unsigned k1 = (n - 1) >> 1, k2 = n >> 1;  // median ranks (0-based)
        int v1 = -1, v2 = -1;
        if (k1 >= pexcl && k1 < csum) {
            unsigned run = pexcl;
            #pragma unroll
            for (int i = 0; i < 8; i++) { run += c[i]; if (v1 < 0 && k1 < run) v1 = lane * 8 + i; }
        }
        if (k2 >= pexcl && k2 < csum) {
            unsigned run = pexcl;
            #pragma unroll
            for (int i = 0; i < 8; i++) { run += c[i]; if (v2 < 0 && k2 < run) v2 = lane * 8 + i; }
        }
        v1 = __reduce_max_sync(FULL, v1);
        v2 = __reduce_max_sync(FULL, v2);

        if (lane == 0) {
            int bb = blk / 3, cc = blk - bb * 3;
            double dn   = (double)n;
            double mean = (double)tsum / dn;
            double var  = (double)tsq / dn - mean * mean;
            float stdv  = (float)sqrt(var > 0.0 ? var : 0.0);
            float med   = 0.5f * (float)(v1 + v2);
            float* o = out + ((size_t)bb * 4 + r) * 9;
            o[cc]     = (float)mean;
            o[3 + cc] = stdv;
            o[6 + cc] = med;
        }
    }
}

extern "C" void kernel_launch(void* const* d_in, const int* in_sizes, int n_in,
                              void* d_out, int out_size) {
    const float* img = (const float*)d_in[0];
    float* out = (float*)d_out;
    const int nblk = in_sizes[0] / 16384;  // B * 3 CTAs (one per batch-channel)
    radial_tokenizer_kernel<<<nblk, 256, SMEM_BYTES>>>(img, out);
}

// round 8
// speedup vs baseline: 1.8619x; 1.0490x over previous
#include <cuda_runtime.h>
#include <cstdint>
#include <math.h>

#define FULL 0xffffffffu

// ---------------- compile-time row-segment table ----------------
// One entry per (ring, image row) covering the annulus intersection as up to
// two x-intervals merged into a single 0..npx-1 pixel index space:
//   x = p + (p < n1 ? lo1 : lo2m)      (lo2m = lo2 - n1)
// Entries sorted by ring then y; ws[] = equal-pixel contiguous warp partition.
struct Tab {
    uint32_t A[336];   // lo1 | n1<<8 | lo2m<<16
    uint32_t B[336];   // y | npx<<8 | ring<<16
    int n;
    int ws[9];
};

constexpr int cisqrt(int v) {
    int a = 0;
    while ((a + 1) * (a + 1) <= v) a++;
    return a;
}

constexpr Tab mk_tab() {
    Tab t{};
    int idx = 0;
    int px[336] = {};
    for (int r = 0; r < 4; r++) {
        const int R1 = (r + 1) * 16, r0 = r * 16;
        for (int y = 0; y < 128; y++) {
            const int dy = y - 64;
            const int ao = R1 * R1 - dy * dy;
            if (ao < 0) continue;
            const int a = cisqrt(ao);
            const int hole = r0 * r0 - dy * dy;
            int lo1 = 0, n1 = 0, lo2m = 0, npx = 0;
            if (hole >= 0) {                       // annulus hole on this row
                const int b = cisqrt(hole);
                lo1 = 64 - a;
                n1  = a - b;            if (n1 < 0) n1 = 0;
                const int lo2 = 65 + b;
                int hi2 = 64 + a;       if (hi2 > 127) hi2 = 127;
                int n2 = hi2 - lo2 + 1; if (n2 < 0) n2 = 0;
                npx  = n1 + n2;
                lo2m = lo2 - n1;
            } else {                               // full span
                lo1 = 64 - a;
                int hi = 64 + a;        if (hi > 127) hi = 127;
                n1  = hi - lo1 + 1;
                npx = n1;
                lo2m = 0;
            }
            if (npx <= 0) continue;
            t.A[idx] = (uint32_t)lo1 | ((uint32_t)n1 << 8) | ((uint32_t)lo2m << 16);
            t.B[idx] = (uint32_t)y   | ((uint32_t)npx << 8) | ((uint32_t)r << 16);
            px[idx] = npx;
            idx++;
        }
    }
    t.n = idx;
    int total = 0;
    for (int i = 0; i < idx; i++) total += px[i];
    t.ws[0] = 0;
    int cum = 0, w = 1;
    for (int i = 0; i < idx && w < 8; i++) {
        cum += px[i];
        while (w < 8 && cum * 8 >= total * w) { t.ws[w] = i + 1; w++; }
    }
    for (int k = w; k < 9; k++) t.ws[k] = idx;
    t.ws[8] = idx;
    return t;
}

__constant__ Tab c_tab = mk_tab();

// SMEM layout (dynamic):
//   sh4   : 32768 bytes  (8 warps x 128 byte-rows x 32 lanes; 2 bins/byte, nibbles)
//   hist4 : 4*256 u32    (per-ring combined histogram)
static constexpr int SMEM_BYTES = 32768 + 4 * 256 * 4;  // 36864

// reduce own nibble slab into hist4[ring] (smem atomics) and re-zero it
__device__ __forceinline__ void flush_slab(uint8_t* myh, int lane,
                                           uint32_t* hist4, int ring) {
    uint32_t* rh = hist4 + ring * 256;
    const uint4 z = make_uint4(0u, 0u, 0u, 0u);
    #pragma unroll
    for (int j = 0; j < 4; j++) {
        const int bp = lane + j * 32;              // byte-row 0..127
        uint4* q = (uint4*)(myh + bp * 32);
        uint4 a = q[0], b = q[1];
        unsigned lo = 0, hi = 0, w;
        #define ACC(W) w = (W); \
            lo = __dp4a(w & 0x0F0F0F0Fu, 0x01010101u, lo); \
            hi = __dp4a((w >> 4) & 0x0F0F0F0Fu, 0x01010101u, hi);
        ACC(a.x) ACC(a.y) ACC(a.z) ACC(a.w)
        ACC(b.x) ACC(b.y) ACC(b.z) ACC(b.w)
        #undef ACC
        q[0] = z; q[1] = z;
        atomicAdd(rh + 2 * bp,     lo);
        atomicAdd(rh + 2 * bp + 1, hi);
    }
    __syncwarp();
}

__global__ __launch_bounds__(256, 6)
void radial_tokenizer_kernel(const float* __restrict__ img, float* __restrict__ out) {
    extern __shared__ uint8_t smem[];
    uint8_t*  sh4   = smem;                        // 32768
    uint32_t* hist4 = (uint32_t*)(smem + 32768);   // 1024 words

    const int tid  = threadIdx.x;
    const int lane = tid & 31;
    const int wid  = tid >> 5;
    const int blk  = blockIdx.x;                   // b*3 + c

    // ---- Phase 0: zero nibble slabs + hist4 ----
    {
        const uint4 z = make_uint4(0u, 0u, 0u, 0u);
        uint4* z4 = (uint4*)sh4;
        #pragma unroll
        for (int i = 0; i < 8; i++) z4[i * 256 + tid] = z;
        ((uint4*)hist4)[tid] = z;
    }
    __syncthreads();

    // ---- Phase B: per-warp privatized nibble histogram over balanced range ----
    uint8_t* myh  = sh4 + wid * 4096;
    uint8_t* myhl = myh + lane;
    const float* base = img + (size_t)blk * 16384;

    const int i0 = c_tab.ws[wid];
    const int i1 = c_tab.ws[wid + 1];
    if (i0 < i1) {
        int curRing = (int)(c_tab.B[i0] >> 16);
        for (int i = i0; i < i1; i++) {
            const uint32_t A = c_tab.A[i];
            const uint32_t Bv = c_tab.B[i];
            const int ring = (int)(Bv >> 16);
            if (ring != curRing) {                 // warp-uniform, rare
                flush_slab(myh, lane, hist4, curRing);
                curRing = ring;
            }
            const int y    = Bv & 255;
            const int npx  = (Bv >> 8) & 255;
            const int lo1  = A & 255;
            const int n1   = (A >> 8) & 255;
            const int lo2m = (int)(A >> 16);
            const float* row = base + (y << 7);

            for (int p0 = 0; p0 < npx; p0 += 32) { // uniform trip: 1..3 iters
                const int p = p0 + lane;
                const int x = p + ((p < n1) ? lo1 : lo2m);
                if (p < npx) {
                    const float f = row[x];
                    const int v = (int)(f * 255.0f);          // floor, 0..254
                    const unsigned off = ((unsigned)(v * 16)) & 0xFE0u;
                    const unsigned inc = (unsigned)(v & 1) * 15u + 1u; // 1 or 16
                    myhl[off] = (uint8_t)(myhl[off] + inc);
                }
            }
        }
        flush_slab(myh, lane, hist4, curRing);
    }
    __syncthreads();

    // ---- Phase D: stats (mean/std/median) — one warp per ring ----
    if (wid < 4) {
        const int r = wid;
        unsigned c[8];
        unsigned cnt = 0, sum = 0, sq = 0;
        #pragma unroll
        for (int i = 0; i < 8; i++) {
            const unsigned v = (unsigned)lane * 8u + i;
            c[i] = hist4[r * 256 + v];
            cnt += c[i];
            sum += c[i] * v;
            sq  += c[i] * v * v;
        }
        // inclusive warp scan of counts
        unsigned csum = cnt;
        #pragma unroll
        for (int d = 1; d < 32; d <<= 1) {
            const unsigned t = __shfl_up_sync(FULL, csum, d);
            if (lane >= d) csum += t;
        }
        const unsigned pexcl = csum - cnt;
        const unsigned n    = __shfl_sync(FULL, csum, 31);
        const unsigned tsum = __reduce_add_sync(FULL, sum);
        const unsigned tsq  = __reduce_add_sync(FULL, sq);

        const unsigned k1 = (n - 1) >> 1, k2 = n >> 1;  // median ranks (0-based)
        int v1 = -1, v2 = -1;
        if (k1 >= pexcl && k1 < csum) {
            unsigned run = pexcl;
            #pragma unroll
            for (int i = 0; i < 8; i++) { run += c[i]; if (v1 < 0 && k1 < run) v1 = lane * 8 + i; }
        }
        if (k2 >= pexcl && k2 < csum) {
            unsigned run = pexcl;
            #pragma unroll
            for (int i = 0; i < 8; i++) { run += c[i]; if (v2 < 0 && k2 < run) v2 = lane * 8 + i; }
        }
        v1 = __reduce_max_sync(FULL, v1);
        v2 = __reduce_max_sync(FULL, v2);

        if (lane == 0) {
            const int bb = blk / 3, cc = blk - bb * 3;
            const double dn   = (double)n;
            const double mean = (double)tsum / dn;
            const double var  = (double)tsq / dn - mean * mean;
            const float stdv  = (float)sqrt(var > 0.0 ? var : 0.0);
            const float med   = 0.5f * (float)(v1 + v2);
            float* o = out + ((size_t)bb * 4 + r) * 9;
            o[cc]     = (float)mean;
            o[3 + cc] = stdv;
            o[6 + cc] = med;
        }
    }
}

extern "C" void kernel_launch(void* const* d_in, const int* in_sizes, int n_in,
                              void* d_out, int out_size) {
    const float* img = (const float*)d_in[0];
    float* out = (float*)d_out;
    const int nblk = in_sizes[0] / 16384;  // B * 3 CTAs (one per batch-channel)
    radial_tokenizer_kernel<<<nblk, 256, SMEM_BYTES>>>(img, out);
}

// round 9
// speedup vs baseline: 3.6022x; 1.9347x over previous
#include <cuda_runtime.h>
#include <cstdint>
#include <math.h>

#define FULL 0xffffffffu

// ---------------- compile-time flat pixel list ----------------
// Ring-ordered (ring, then y, then x) list of pixel indices (y*128+x) for the
// 4 annuli. Pre-partitioned into 8 equal-pixel warp ranges; each warp gets at
// most 2 "runs" (a run = contiguous pixels of ONE ring), each padded to a
// multiple of 32 with 0xFFFF sentinels.
struct Built {
    uint16_t px[13568];
    int off[8][2];     // start index into px
    int niter[8][2];   // padded length / 32  (0 = no run)
    int ringv[8][2];   // ring id of run
};

constexpr Built mk() {
    Built b{};
    uint16_t raw[13568] = {};
    int rc[5] = {};
    int n = 0;
    for (int r = 0; r < 4; r++) {
        rc[r] = n;
        const int r1 = (r + 1) * 16, r0 = r * 16;
        for (int y = 0; y < 128; y++)
            for (int x = 0; x < 128; x++) {
                const int d2 = (x - 64) * (x - 64) + (y - 64) * (y - 64);
                if (d2 <= r1 * r1 && d2 > r0 * r0) { raw[n] = (uint16_t)(y * 128 + x); n++; }
            }
    }
    rc[4] = n;
    int pos = 0, outp = 0;
    for (int w = 0; w < 8; w++) {
        const int end = ((w + 1) * n) / 8;
        int rn = 0;
        while (pos < end && rn < 2) {
            int r = 0;
            for (int q = 0; q < 4; q++) if (pos >= rc[q] && pos < rc[q + 1]) r = q;
            const int stop = (end < rc[r + 1]) ? end : rc[r + 1];
            const int cnt = stop - pos;
            const int pad = ((cnt + 31) / 32) * 32;
            b.off[w][rn] = outp;
            b.niter[w][rn] = pad / 32;
            b.ringv[w][rn] = r;
            for (int i = 0; i < pad; i++)
                b.px[outp + i] = (i < cnt) ? raw[pos + i] : (uint16_t)0xFFFF;
            outp += pad;
            pos = stop;
            rn++;
        }
    }
    return b;
}

constexpr Built g_built_h = mk();
__device__ const uint16_t g_px[13568] = {};   // placeholder replaced below

// We need the actual data in device memory; initialize a device array from the
// host constexpr object (const-initializer, no runtime alloc).
struct PxArr { uint16_t v[13568]; };
constexpr PxArr mk_pxarr() {
    PxArr a{};
    for (int i = 0; i < 13568; i++) a.v[i] = g_built_h.px[i];
    return a;
}
__device__ const PxArr g_pxa = mk_pxarr();

struct RunTab { int off[8][2]; int niter[8][2]; int ringv[8][2]; };
constexpr RunTab mk_runs() {
    RunTab t{};
    for (int w = 0; w < 8; w++)
        for (int rn = 0; rn < 2; rn++) {
            t.off[w][rn]   = g_built_h.off[w][rn];
            t.niter[w][rn] = g_built_h.niter[w][rn];
            t.ringv[w][rn] = g_built_h.ringv[w][rn];
        }
    return t;
}
__constant__ RunTab c_runs = mk_runs();

// SMEM layout (dynamic):
//   sh4   : 32768 bytes  (8 warps x 128 byte-rows x 32 lanes; 2 bins/byte, nibbles)
//   hist4 : 4*256 u32    (per-ring combined histogram)
static constexpr int SMEM_BYTES = 32768 + 4 * 256 * 4;  // 36864

// reduce own nibble slab into hist4[ring] (smem atomics) and re-zero it
__device__ __forceinline__ void flush_slab(uint8_t* myh, int lane,
                                           uint32_t* hist4, int ring) {
    uint32_t* rh = hist4 + ring * 256;
    const uint4 z = make_uint4(0u, 0u, 0u, 0u);
    #pragma unroll
    for (int j = 0; j < 4; j++) {
        const int bp = lane + j * 32;              // byte-row 0..127
        uint4* q = (uint4*)(myh + bp * 32);
        uint4 a = q[0], b = q[1];
        unsigned lo = 0, hi = 0, w;
        #define ACC(W) w = (W); \
            lo = __dp4a(w & 0x0F0F0F0Fu, 0x01010101u, lo); \
            hi = __dp4a((w >> 4) & 0x0F0F0F0Fu, 0x01010101u, hi);
        ACC(a.x) ACC(a.y) ACC(a.z) ACC(a.w)
        ACC(b.x) ACC(b.y) ACC(b.z) ACC(b.w)
        #undef ACC
        q[0] = z; q[1] = z;
        atomicAdd(rh + 2 * bp,     lo);
        atomicAdd(rh + 2 * bp + 1, hi);
    }
    __syncwarp();
}

__global__ __launch_bounds__(256, 6)
void radial_tokenizer_kernel(const float* __restrict__ img, float* __restrict__ out) {
    extern __shared__ uint8_t smem[];
    uint8_t*  sh4   = smem;                        // 32768
    uint32_t* hist4 = (uint32_t*)(smem + 32768);   // 1024 words

    const int tid  = threadIdx.x;
    const int lane = tid & 31;
    const int wid  = tid >> 5;
    const int blk  = blockIdx.x;                   // b*3 + c

    // ---- Phase 0: zero nibble slabs + hist4 ----
    {
        const uint4 z = make_uint4(0u, 0u, 0u, 0u);
        uint4* z4 = (uint4*)sh4;
        #pragma unroll
        for (int i = 0; i < 8; i++) z4[i * 256 + tid] = z;
        ((uint4*)hist4)[tid] = z;
    }
    __syncthreads();

    // ---- Phase B: flat pixel-list loop, per-warp privatized nibble hist ----
    uint8_t* myh  = sh4 + wid * 4096;
    uint8_t* myhl = myh + lane;
    const float* base = img + (size_t)blk * 16384;

    #pragma unroll
    for (int rn = 0; rn < 2; rn++) {
        const int ni = c_runs.niter[wid][rn];
        if (ni == 0) continue;                     // warp-uniform
        const int ring = c_runs.ringv[wid][rn];
        const uint16_t* lp = g_pxa.v + c_runs.off[wid][rn] + lane;

        #pragma unroll 4
        for (int it = 0; it < ni; it++) {
            const unsigned idx = lp[it * 32];      // L1-hot (shared by all CTAs)
            if (idx != 0xFFFFu) {
                const float f = __ldg(base + idx);
                const int v = (int)(f * 255.0f);               // floor, 0..254
                const unsigned off = ((unsigned)(v * 16)) & 0xFE0u;
                const unsigned inc = (unsigned)(v & 1) * 15u + 1u;  // 1 or 16
                myhl[off] = (uint8_t)(myhl[off] + inc);
            }
        }
        flush_slab(myh, lane, hist4, ring);
    }
    __syncthreads();

    // ---- Phase D: stats (mean/std/median) — one warp per ring ----
    if (wid < 4) {
        const int r = wid;
        unsigned c[8];
        unsigned cnt = 0, sum = 0, sq = 0;
        #pragma unroll
        for (int i = 0; i < 8; i++) {
            const unsigned v = (unsigned)lane * 8u + i;
            c[i] = hist4[r * 256 + v];
            cnt += c[i];
            sum += c[i] * v;
            sq  += c[i] * v * v;
        }
        // inclusive warp scan of counts
        unsigned csum = cnt;
        #pragma unroll
        for (int d = 1; d < 32; d <<= 1) {
            const unsigned t = __shfl_up_sync(FULL, csum, d);
            if (lane >= d) csum += t;
        }
        const unsigned pexcl = csum - cnt;
        const unsigned n    = __shfl_sync(FULL, csum, 31);
        const unsigned tsum = __reduce_add_sync(FULL, sum);
        const unsigned tsq  = __reduce_add_sync(FULL, sq);

        const unsigned k1 = (n - 1) >> 1, k2 = n >> 1;  // median ranks (0-based)
        int v1 = -1, v2 = -1;
        if (k1 >= pexcl && k1 < csum) {
            unsigned run = pexcl;
            #pragma unroll
            for (int i = 0; i < 8; i++) { run += c[i]; if (v1 < 0 && k1 < run) v1 = lane * 8 + i; }
        }
        if (k2 >= pexcl && k2 < csum) {
            unsigned run = pexcl;
            #pragma unroll
            for (int i = 0; i < 8; i++) { run += c[i]; if (v2 < 0 && k2 < run) v2 = lane * 8 + i; }
        }
        v1 = __reduce_max_sync(FULL, v1);
        v2 = __reduce_max_sync(FULL, v2);

        if (lane == 0) {
            const int bb = blk / 3, cc = blk - bb * 3;
            const double dn   = (double)n;
            const double mean = (double)tsum / dn;
            const double var  = (double)tsq / dn - mean * mean;
            const float stdv  = (float)sqrt(var > 0.0 ? var : 0.0);
            const float med   = 0.5f * (float)(v1 + v2);
            float* o = out + ((size_t)bb * 4 + r) * 9;
            o[cc]     = (float)mean;
            o[3 + cc] = stdv;
            o[6 + cc] = med;
        }
    }
}

extern "C" void kernel_launch(void* const* d_in, const int* in_sizes, int n_in,
                              void* d_out, int out_size) {
    const float* img = (const float*)d_in[0];
    float* out = (float*)d_out;
    const int nblk = in_sizes[0] / 16384;  // B * 3 CTAs (one per batch-channel)
    radial_tokenizer_kernel<<<nblk, 256, SMEM_BYTES>>>(img, out);
}

// round 10
// speedup vs baseline: 3.9768x; 1.1040x over previous
#include <cuda_runtime.h>
#include <cstdint>
#include <math.h>

#define FULL 0xffffffffu

// ---------------- compile-time flat pixel list (pair-vectorized) ----------------
// Ring-ordered list of pixel indices for the 4 annuli, partitioned into 8
// equal-pixel warp ranges; each warp has at most 2 runs (one ring each), each
// padded to a multiple of 64 (so u32-pair index loads are uniform) with 0xFFFF.
struct Built {
    uint16_t px[14336];
    int off[8][2];       // start element in px
    int ni2[8][2];       // iterations of 64px (0 = no run)
    int rez[8][2];       // 1 = re-zero slab after flush (another run follows)
    int runid[8][2];
    int ringOfRun[16];
    int nruns;
    int ok;
};

constexpr Built mk() {
    Built b{};
    b.ok = 1;
    uint16_t raw[14336] = {};
    int rc[5] = {};
    int n = 0;
    for (int r = 0; r < 4; r++) {
        rc[r] = n;
        const int r1 = (r + 1) * 16, r0 = r * 16;
        for (int y = 0; y < 128; y++)
            for (int x = 0; x < 128; x++) {
                const int d2 = (x - 64) * (x - 64) + (y - 64) * (y - 64);
                if (d2 <= r1 * r1 && d2 > r0 * r0) { raw[n] = (uint16_t)(y * 128 + x); n++; }
            }
    }
    rc[4] = n;
    int pos = 0, outp = 0, rid = 0;
    for (int w = 0; w < 8; w++) {
        const int end = ((w + 1) * n) / 8;
        int rn = 0;
        while (pos < end) {
            if (rn >= 2) { b.ok = 0; break; }
            int r = 0;
            for (int q = 0; q < 4; q++) if (pos >= rc[q] && pos < rc[q + 1]) r = q;
            const int stop = (end < rc[r + 1]) ? end : rc[r + 1];
            const int cnt = stop - pos;
            const int pad = ((cnt + 63) / 64) * 64;
            if (outp + pad > 14336 || rid >= 16) { b.ok = 0; break; }
            b.off[w][rn] = outp;
            b.ni2[w][rn] = pad / 64;
            b.runid[w][rn] = rid;
            b.ringOfRun[rid] = r;
            for (int i = 0; i < pad; i++)
                b.px[outp + i] = (i < cnt) ? raw[pos + i] : (uint16_t)0xFFFF;
            outp += pad; pos = stop; rid++; rn++;
        }
        if (rn == 2) b.rez[w][0] = 1;    // first run's slab must be re-zeroed
    }
    b.nruns = rid;
    return b;
}

constexpr Built g_built = mk();
static_assert(g_built.ok == 1, "partition failed");
static_assert(g_built.nruns <= 16, "too many runs");
constexpr int NRUNS = g_built.nruns;

struct PxArr { uint16_t v[14336]; };
constexpr PxArr mk_px() {
    PxArr a{};
    for (int i = 0; i < 14336; i++) a.v[i] = g_built.px[i];
    return a;
}
__device__ const PxArr g_pxa = mk_px();

struct RunTab { int off[8][2]; int ni2[8][2]; int rez[8][2]; int runid[8][2]; int ringOfRun[16]; };
constexpr RunTab mk_rt() {
    RunTab t{};
    for (int w = 0; w < 8; w++)
        for (int rn = 0; rn < 2; rn++) {
            t.off[w][rn] = g_built.off[w][rn];
            t.ni2[w][rn] = g_built.ni2[w][rn];
            t.rez[w][rn] = g_built.rez[w][rn];
            t.runid[w][rn] = g_built.runid[w][rn];
        }
    for (int k = 0; k < 16; k++) t.ringOfRun[k] = g_built.ringOfRun[k];
    return t;
}
__constant__ RunTab c_rt = mk_rt();

// SMEM layout (dynamic):
//   slabs : 8 warps x 4096 B   (32 v-rows x 32 lanes x u32; 8 nibble bins/word)
//   wsum  : NRUNS x 128 u32    (per-run 256 bins as packed u16 pairs)
static constexpr int SMEM_BYTES = 8 * 4096 + NRUNS * 512;

// REDUX flush: per-warp slab -> wsum[run] (256 bins as u16 pairs), no atomics.
// word (row r, lane): nibble k = count of bin v = 8r+k for this lane.
// stored word c at row r: low u16 = bin 8r+c, high u16 = bin 8r+c+4.
__device__ __forceinline__ void flush(uint32_t* slab, int lane, uint32_t* dst, int rez) {
    uint32_t o0 = 0, o1 = 0, o2 = 0, o3 = 0;
    #pragma unroll
    for (int r = 0; r < 32; r++) {
        const uint32_t w = slab[r * 32 + lane];
        if (rez) slab[r * 32 + lane] = 0u;
        const unsigned s0 = __reduce_add_sync(FULL, w & 0x000F000Fu);
        const unsigned s1 = __reduce_add_sync(FULL, (w >> 4) & 0x000F000Fu);
        const unsigned s2 = __reduce_add_sync(FULL, (w >> 8) & 0x000F000Fu);
        const unsigned s3 = __reduce_add_sync(FULL, (w >> 12) & 0x000F000Fu);
        if (lane == r) { o0 = s0; o1 = s1; o2 = s2; o3 = s3; }
    }
    ((uint4*)dst)[lane] = make_uint4(o0, o1, o2, o3);
    __syncwarp();
}

__global__ __launch_bounds__(256, 6)
void radial_tokenizer_kernel(const float* __restrict__ img, float* __restrict__ out) {
    extern __shared__ uint8_t smem[];
    uint32_t* wsum = (uint32_t*)(smem + 8 * 4096);

    const int tid  = threadIdx.x;
    const int lane = tid & 31;
    const int wid  = tid >> 5;
    const int blk  = blockIdx.x;                   // b*3 + c

    // ---- Phase 0: zero slabs ----
    {
        const uint4 z = make_uint4(0u, 0u, 0u, 0u);
        uint4* z4 = (uint4*)smem;
        #pragma unroll
        for (int i = 0; i < 8; i++) z4[i * 256 + tid] = z;
    }
    __syncthreads();

    // ---- Phase B: conflict-free nibble-word histogram, pair-vectorized ----
    uint32_t* slab = (uint32_t*)(smem + wid * 4096);
    uint32_t* slabw = slab + lane;                 // lane-owned column (bank==lane)
    const float* base = img + (size_t)blk * 16384;

    #pragma unroll
    for (int rn = 0; rn < 2; rn++) {
        const int ni2 = c_rt.ni2[wid][rn];
        if (ni2 == 0) continue;                    // warp-uniform
        const uint32_t* lp = (const uint32_t*)(g_pxa.v + c_rt.off[wid][rn]) + lane;

        #pragma unroll 4
        for (int it = 0; it < ni2; it++) {
            const uint32_t two = lp[it * 32];
            const unsigned i1 = two & 0xFFFFu;
            const unsigned i2 = two >> 16;
            if (i1 != 0xFFFFu) {
                const float f = __ldg(base + i1);
                const int v = (int)(f * 255.0f);               // floor, 0..254
                const unsigned widx = (unsigned)(v & 0xF8) << 2;   // (v>>3)*32 words
                const unsigned sh = (unsigned)(v & 7) << 2;
                slabw[widx] += (1u << sh);
            }
            if (i2 != 0xFFFFu) {
                const float f = __ldg(base + i2);
                const int v = (int)(f * 255.0f);
                const unsigned widx = (unsigned)(v & 0xF8) << 2;
                const unsigned sh = (unsigned)(v & 7) << 2;
                slabw[widx] += (1u << sh);
            }
        }
        flush(slab, lane, wsum + c_rt.runid[wid][rn] * 128, c_rt.rez[wid][rn]);
    }
    __syncthreads();

    // ---- Phase D: stats (mean/std/median) — one warp per ring ----
    if (wid < 4) {
        uint4 acc = make_uint4(0u, 0u, 0u, 0u);
        #pragma unroll
        for (int k = 0; k < NRUNS; k++) {
            if (c_rt.ringOfRun[k] == wid) {        // packed-u16 add, no carry (<=5629)
                const uint4 t = ((const uint4*)(wsum + k * 128))[lane];
                acc.x += t.x; acc.y += t.y; acc.z += t.z; acc.w += t.w;
            }
        }
        unsigned c[8];
        c[0] = acc.x & 0xFFFFu; c[1] = acc.y & 0xFFFFu;
        c[2] = acc.z & 0xFFFFu; c[3] = acc.w & 0xFFFFu;
        c[4] = acc.x >> 16;     c[5] = acc.y >> 16;
        c[6] = acc.z >> 16;     c[7] = acc.w >> 16;

        unsigned cnt = 0, sum = 0, sq = 0;
        #pragma unroll
        for (int i = 0; i < 8; i++) {
            const unsigned v = (unsigned)lane * 8u + i;
            cnt += c[i];
            sum += c[i] * v;
            sq  += c[i] * v * v;
        }
        // inclusive warp scan of counts
        unsigned csum = cnt;
        #pragma unroll
        for (int d = 1; d < 32; d <<= 1) {
            const unsigned t = __shfl_up_sync(FULL, csum, d);
            if (lane >= d) csum += t;
        }
        const unsigned pexcl = csum - cnt;
        const unsigned n    = __shfl_sync(FULL, csum, 31);
        const unsigned tsum = __reduce_add_sync(FULL, sum);
        const unsigned tsq  = __reduce_add_sync(FULL, sq);

        const unsigned k1 = (n - 1) >> 1, k2 = n >> 1;  // median ranks (0-based)
        int v1 = -1, v2 = -1;
        if (k1 >= pexcl && k1 < csum) {
            unsigned run = pexcl;
            #pragma unroll
            for (int i = 0; i < 8; i++) { run += c[i]; if (v1 < 0 && k1 < run) v1 = lane * 8 + i; }
        }
        if (k2 >= pexcl && k2 < csum) {
            unsigned run = pexcl;
            #pragma unroll
            for (int i = 0; i < 8; i++) { run += c[i]; if (v2 < 0 && k2 < run) v2 = lane * 8 + i; }
        }
        v1 = __reduce_max_sync(FULL, v1);
        v2 = __reduce_max_sync(FULL, v2);

        if (lane == 0) {
            const int bb = blk / 3, cc = blk - bb * 3;
            const double dn   = (double)n;
            const double mean = (double)tsum / dn;
            const double var  = (double)tsq / dn - mean * mean;
            const float stdv  = (float)sqrt(var > 0.0 ? var : 0.0);
            const float med   = 0.5f * (float)(v1 + v2);
            float* o = out + ((size_t)bb * 4 + wid) * 9;
            o[cc]     = (float)mean;
            o[3 + cc] = stdv;
            o[6 + cc] = med;
        }
    }
}

extern "C" void kernel_launch(void* const* d_in, const int* in_sizes, int n_in,
                              void* d_out, int out_size) {
    const float* img = (const float*)d_in[0];
    float* out = (float*)d_out;
    const int nblk = in_sizes[0] / 16384;  // B * 3 CTAs (one per batch-channel)
    radial_tokenizer_kernel<<<nblk, 256, SMEM_BYTES>>>(img, out);
}